// round 1
// baseline (speedup 1.0000x reference)
#include <cuda_runtime.h>

// ---------------- problem constants ----------------
#define B_SZ   4
#define C_IN   32
#define C_OUT  32
#define HW_DIM 256
#define PLANE  (HW_DIM * HW_DIM)   // 65536
#define KTAPS  9

// conv tile
#define TW 64
#define TH 16
#define IW 66
#define IH 18

#define SU_FLOATS (C_IN * IH * IW)          // 38016
#define SW_FLOATS (KTAPS * C_IN * C_OUT)    // 9216
#define SS_FLOATS (IH * IW)                 // 1188
#define SB_FLOATS 32
#define SMEM_FLOATS (SU_FLOATS + SW_FLOATS + SS_FLOATS + SB_FLOATS)
#define SMEM_BYTES  (SMEM_FLOATS * 4)       // 193808 B

// scratch for log0 scale factors (static __device__: no allocations allowed)
__device__ float g_S[B_SZ * PLANE];

// ---------------- packed f32x2 helpers ----------------
__device__ __forceinline__ unsigned long long pack2(float a) {
    unsigned long long r;
    asm("mov.b64 %0, {%1, %1};" : "=l"(r) : "f"(a));
    return r;
}
__device__ __forceinline__ void ffma2(unsigned long long& d,
                                      unsigned long long a,
                                      unsigned long long b) {
    asm("fma.rn.f32x2 %0, %1, %2, %0;" : "+l"(d) : "l"(a), "l"(b));
}
__device__ __forceinline__ void unpack2(unsigned long long v, float& lo, float& hi) {
    asm("mov.b64 {%0, %1}, %2;" : "=f"(lo), "=f"(hi) : "l"(v));
}

// ---------------- kernel 1: log0 scale per pixel ----------------
// S[b,h,w] = atanh(clip(0.1*n, 0, 1-1e-6)) / (0.1*n),  n = max(||x[b,:,h,w]||, 1e-7)
__global__ void log0_scale_kernel(const float* __restrict__ x) {
    int pid = blockIdx.x * blockDim.x + threadIdx.x;   // 0 .. B*PLANE-1
    int b = pid >> 16;
    int p = pid & (PLANE - 1);
    const float* xb = x + ((size_t)b * C_IN) * PLANE + p;
    float ss = 0.f;
#pragma unroll
    for (int c = 0; c < C_IN; c++) {
        float v = xb[(size_t)c * PLANE];
        ss += v * v;
    }
    float n = fmaxf(sqrtf(ss), 1e-7f);
    float a = fminf(0.1f * n, 1.0f - 1e-6f);
    g_S[pid] = atanhf(a) / (0.1f * n);
}

// ---------------- kernel 2: fused conv + bias + relu + exp0 ----------------
__global__ __launch_bounds__(256, 1)
void pvconv_kernel(const float* __restrict__ x,
                   const float* __restrict__ Wk,
                   const float* __restrict__ bias,
                   float* __restrict__ out) {
    extern __shared__ float sm[];
    float* su  = sm;                         // [cin][IH][IW] scaled inputs
    float* sw  = su + SU_FLOATS;             // [k][cin][cout] transposed weights
    float* ssc = sw + SW_FLOATS;             // [IH][IW] log0 scales
    float* sb  = ssc + SS_FLOATS;            // [32] bias

    const int tid = threadIdx.x;
    const int b  = blockIdx.z;
    const int r0 = blockIdx.y * TH;
    const int c0 = blockIdx.x * TW;

    // --- phase 1: weights (transpose [k][o][c] -> [k][c][o]), bias, scale tile ---
    for (int idx = tid; idx < SW_FLOATS; idx += 256) {
        int k = idx >> 10;
        int rem = idx & 1023;
        int c = rem >> 5;
        int o = rem & 31;
        sw[idx] = Wk[(k << 10) + (o << 5) + c];
    }
    if (tid < 32) sb[tid] = bias[tid];
    {
        const float* Sb = g_S + ((size_t)b << 16);
        for (int idx = tid; idx < SS_FLOATS; idx += 256) {
            int rr = idx / IW;
            int cc = idx - rr * IW;
            int gh = r0 - 1 + rr, gw = c0 - 1 + cc;
            float v = 0.f;
            if ((unsigned)gh < (unsigned)HW_DIM && (unsigned)gw < (unsigned)HW_DIM)
                v = Sb[(gh << 8) + gw];
            ssc[idx] = v;
        }
    }
    __syncthreads();

    // --- phase 2: scaled input tile u = S * x (zero padding in halo) ---
    {
        const float* xb = x + (((size_t)b * C_IN) << 16);
        for (int idx = tid; idx < SU_FLOATS; idx += 256) {
            int cin = idx / (IH * IW);
            int rem = idx - cin * (IH * IW);
            int rr = rem / IW;
            int cc = rem - rr * IW;
            int gh = r0 - 1 + rr, gw = c0 - 1 + cc;
            float v = 0.f;
            if ((unsigned)gh < (unsigned)HW_DIM && (unsigned)gw < (unsigned)HW_DIM)
                v = xb[((size_t)cin << 16) + (gh << 8) + gw] * ssc[rem];
            su[idx] = v;
        }
    }
    __syncthreads();

    // --- phase 3: compute. Each thread: 4 pixels x 32 couts (as 16 f32x2 pairs) ---
    const int lane = tid & 31;
    const int warp = tid >> 5;
    const int lr0 = warp << 1;   // this warp's 2 output rows

    unsigned long long acc[4][16];
#pragma unroll
    for (int p = 0; p < 4; p++)
#pragma unroll
        for (int t = 0; t < 16; t++) acc[p][t] = 0ull;

#pragma unroll 1
    for (int k = 0; k < KTAPS; k++) {
        const int ki = k / 3;
        const int kj = k - ki * 3;
        const float* ub = su + (lr0 + ki) * IW + lane + kj;
        const ulonglong2* wb = (const ulonglong2*)(sw + (k << 10));
#pragma unroll 4
        for (int c = 0; c < C_IN; c++) {
            const float* up = ub + c * (IH * IW);
            float a0 = up[0];
            float a1 = up[32];
            float a2 = up[IW];
            float a3 = up[IW + 32];
            unsigned long long pa0 = pack2(a0);
            unsigned long long pa1 = pack2(a1);
            unsigned long long pa2 = pack2(a2);
            unsigned long long pa3 = pack2(a3);
            const ulonglong2* wv = wb + (c << 3);   // 8 x ulonglong2 = 32 couts
#pragma unroll
            for (int t = 0; t < 8; t++) {
                ulonglong2 w = wv[t];
                ffma2(acc[0][2 * t],     pa0, w.x); ffma2(acc[0][2 * t + 1], pa0, w.y);
                ffma2(acc[1][2 * t],     pa1, w.x); ffma2(acc[1][2 * t + 1], pa1, w.y);
                ffma2(acc[2][2 * t],     pa2, w.x); ffma2(acc[2][2 * t + 1], pa2, w.y);
                ffma2(acc[3][2 * t],     pa3, w.x); ffma2(acc[3][2 * t + 1], pa3, w.y);
            }
        }
    }

    // --- phase 4: epilogue: bias + relu + exp0, planar coalesced stores ---
    const int gh_base = r0 + lr0;
    float* outb = out + (((size_t)b * C_OUT) << 16);
#pragma unroll
    for (int p = 0; p < 4; p++) {
        const int gh = gh_base + (p >> 1);
        const int gw = c0 + lane + ((p & 1) << 5);
        float v[32];
#pragma unroll
        for (int t = 0; t < 16; t++) unpack2(acc[p][t], v[2 * t], v[2 * t + 1]);
        float ssum = 0.f;
#pragma unroll
        for (int o = 0; o < 32; o++) {
            float z = fmaxf(v[o] + sb[o], 0.f);
            v[o] = z;
            ssum += z * z;
        }
        float n = fmaxf(sqrtf(ssum), 1e-7f);
        float f = tanhf(0.1f * n) / (0.1f * n);
        float* ob = outb + (gh << 8) + gw;
#pragma unroll
        for (int o = 0; o < 32; o++) ob[(size_t)o << 16] = f * v[o];
    }
}

// ---------------- launch ----------------
extern "C" void kernel_launch(void* const* d_in, const int* in_sizes, int n_in,
                              void* d_out, int out_size) {
    const float* x    = (const float*)d_in[0];
    const float* Wk   = (const float*)d_in[1];
    const float* bias = (const float*)d_in[2];
    float* out = (float*)d_out;

    cudaFuncSetAttribute(pvconv_kernel,
                         cudaFuncAttributeMaxDynamicSharedMemorySize, SMEM_BYTES);

    // kernel 1: per-pixel log0 scale
    log0_scale_kernel<<<(B_SZ * PLANE) / 256, 256>>>(x);

    // kernel 2: fused conv + bias + relu + exp0
    dim3 grid(HW_DIM / TW, HW_DIM / TH, B_SZ);   // (4, 16, 4)
    pvconv_kernel<<<grid, 256, SMEM_BYTES>>>(x, Wk, bias, out);
}

// round 2
// speedup vs baseline: 1.0078x; 1.0078x over previous
#include <cuda_runtime.h>

// ---------------- problem constants ----------------
#define B_SZ   4
#define C_IN   32
#define C_OUT  32
#define HW_DIM 256
#define PLANE  (HW_DIM * HW_DIM)   // 65536
#define KTAPS  9

// conv tile
#define TW 64
#define TH 16
#define IW 66
#define IH 18
#define NTHREADS 512

#define SU_FLOATS (C_IN * IH * IW)          // 38016
#define SW_FLOATS (KTAPS * C_IN * C_OUT)    // 9216
#define SS_FLOATS (IH * IW)                 // 1188
#define SB_FLOATS 32
#define SP_FLOATS (NTHREADS * 4)            // 2048 partial sums for exp0
#define SMEM_FLOATS (SU_FLOATS + SW_FLOATS + SS_FLOATS + SB_FLOATS + SP_FLOATS)
#define SMEM_BYTES  (SMEM_FLOATS * 4)       // ~202 KB

// scratch for log0 scale factors (static __device__: no allocations allowed)
__device__ float g_S[B_SZ * PLANE];

// ---------------- packed f32x2 helpers ----------------
__device__ __forceinline__ unsigned long long pack2(float a) {
    unsigned long long r;
    asm("mov.b64 %0, {%1, %1};" : "=l"(r) : "f"(a));
    return r;
}
__device__ __forceinline__ unsigned long long packab(float a, float b) {
    unsigned long long r;
    asm("mov.b64 %0, {%1, %2};" : "=l"(r) : "f"(a), "f"(b));
    return r;
}
__device__ __forceinline__ void ffma2(unsigned long long& d,
                                      unsigned long long a,
                                      unsigned long long b) {
    asm("fma.rn.f32x2 %0, %1, %2, %0;" : "+l"(d) : "l"(a), "l"(b));
}
__device__ __forceinline__ void unpack2(unsigned long long v, float& lo, float& hi) {
    asm("mov.b64 {%0, %1}, %2;" : "=f"(lo), "=f"(hi) : "l"(v));
}

// ---------------- kernel 1: log0 scale per pixel ----------------
// S[b,h,w] = atanh(clip(0.1*n, 0, 1-1e-6)) / (0.1*n),  n = max(||x[b,:,h,w]||, 1e-7)
__global__ void log0_scale_kernel(const float* __restrict__ x) {
    int pid = blockIdx.x * blockDim.x + threadIdx.x;   // 0 .. B*PLANE-1
    int b = pid >> 16;
    int p = pid & (PLANE - 1);
    const float* xb = x + ((size_t)b * C_IN) * PLANE + p;
    float ss = 0.f;
#pragma unroll
    for (int c = 0; c < C_IN; c++) {
        float v = xb[(size_t)c * PLANE];
        ss += v * v;
    }
    float n = fmaxf(sqrtf(ss), 1e-7f);
    float a = fminf(0.1f * n, 1.0f - 1e-6f);
    g_S[pid] = atanhf(a) / (0.1f * n);
}

// ---------------- kernel 2: fused conv + bias + relu + exp0 ----------------
// 512 threads: warps 0-7 compute couts [0,16), warps 8-15 couts [16,32),
// each thread owns 4 pixels (2 rows x 2 column-halves) of a 64x16 tile.
__global__ __launch_bounds__(NTHREADS, 1)
void pvconv_kernel(const float* __restrict__ x,
                   const float* __restrict__ Wk,
                   const float* __restrict__ bias,
                   float* __restrict__ out) {
    extern __shared__ float sm[];
    float* su    = sm;                        // [cin][IH][IW] scaled inputs
    float* sw    = su + SU_FLOATS;            // [k][cin][cout] transposed weights
    float* ssc   = sw + SW_FLOATS;            // [IH][IW] log0 scales
    float* sb    = ssc + SS_FLOATS;           // [32] bias
    float* spart = sb + SB_FLOATS;            // [4][512] exp0 partial norms

    const int tid = threadIdx.x;
    const int b  = blockIdx.z;
    const int r0 = blockIdx.y * TH;
    const int c0 = blockIdx.x * TW;

    // --- phase 1: weights (transpose [k][o][c] -> [k][c][o]), bias, scale tile ---
    for (int idx = tid; idx < SW_FLOATS; idx += NTHREADS) {
        int k = idx >> 10;
        int rem = idx & 1023;
        int c = rem >> 5;
        int o = rem & 31;
        sw[idx] = Wk[(k << 10) + (o << 5) + c];
    }
    if (tid < 32) sb[tid] = bias[tid];
    {
        const float* Sb = g_S + ((size_t)b << 16);
        for (int idx = tid; idx < SS_FLOATS; idx += NTHREADS) {
            int rr = idx / IW;
            int cc = idx - rr * IW;
            int gh = r0 - 1 + rr, gw = c0 - 1 + cc;
            float v = 0.f;
            if ((unsigned)gh < (unsigned)HW_DIM && (unsigned)gw < (unsigned)HW_DIM)
                v = Sb[(gh << 8) + gw];
            ssc[idx] = v;
        }
    }
    __syncthreads();

    // --- phase 2: scaled input tile u = S * x (zero padding in halo) ---
    {
        const float* xb = x + (((size_t)b * C_IN) << 16);
        for (int idx = tid; idx < SU_FLOATS; idx += NTHREADS) {
            int cin = idx / (IH * IW);
            int rem = idx - cin * (IH * IW);
            int rr = rem / IW;
            int cc = rem - rr * IW;
            int gh = r0 - 1 + rr, gw = c0 - 1 + cc;
            float v = 0.f;
            if ((unsigned)gh < (unsigned)HW_DIM && (unsigned)gw < (unsigned)HW_DIM)
                v = xb[((size_t)cin << 16) + (gh << 8) + gw] * ssc[rem];
            su[idx] = v;
        }
    }
    __syncthreads();

    // --- phase 3: compute. Each thread: 4 pixels x 16 couts (8 f32x2) ---
    const int lane = tid & 31;
    const int warp = tid >> 5;
    const int g    = warp >> 3;        // cout group: 0 -> [0,16), 1 -> [16,32)
    const int wr   = warp & 7;
    const int lr0  = wr << 1;          // this warp-slot's 2 output rows

    unsigned long long acc[4][8];
#pragma unroll
    for (int p = 0; p < 4; p++)
#pragma unroll
        for (int t = 0; t < 8; t++) acc[p][t] = 0ull;

#pragma unroll 1
    for (int k = 0; k < KTAPS; k++) {
        const int ki = k / 3;
        const int kj = k - ki * 3;
        const float* ub = su + (lr0 + ki) * IW + lane + kj;
        const ulonglong2* wb = (const ulonglong2*)(sw + (k << 10) + (g << 4));
#pragma unroll 4
        for (int c = 0; c < C_IN; c++) {
            const float* up = ub + c * (IH * IW);
            unsigned long long pa0 = pack2(up[0]);
            unsigned long long pa1 = pack2(up[32]);
            unsigned long long pa2 = pack2(up[IW]);
            unsigned long long pa3 = pack2(up[IW + 32]);
            const ulonglong2* wv = (const ulonglong2*)((const float*)wb + (c << 5));
#pragma unroll
            for (int t = 0; t < 4; t++) {
                ulonglong2 w = wv[t];
                ffma2(acc[0][2 * t],     pa0, w.x); ffma2(acc[0][2 * t + 1], pa0, w.y);
                ffma2(acc[1][2 * t],     pa1, w.x); ffma2(acc[1][2 * t + 1], pa1, w.y);
                ffma2(acc[2][2 * t],     pa2, w.x); ffma2(acc[2][2 * t + 1], pa2, w.y);
                ffma2(acc[3][2 * t],     pa3, w.x); ffma2(acc[3][2 * t + 1], pa3, w.y);
            }
        }
    }

    // --- phase 4: bias + relu, partial ||.||^2 per cout-half ---
#pragma unroll
    for (int p = 0; p < 4; p++) {
        float s = 0.f;
#pragma unroll
        for (int t = 0; t < 8; t++) {
            float lo, hi;
            unpack2(acc[p][t], lo, hi);
            lo = fmaxf(lo + sb[(g << 4) + 2 * t], 0.f);
            hi = fmaxf(hi + sb[(g << 4) + 2 * t + 1], 0.f);
            s += lo * lo + hi * hi;
            acc[p][t] = packab(lo, hi);
        }
        spart[(p << 9) + tid] = s;
    }
    __syncthreads();

    // --- phase 5: combine halves, exp0 scale, planar coalesced stores ---
    const int gh_base = r0 + lr0;
    float* outb = out + (((size_t)b * C_OUT) << 16) + ((size_t)g << 20); // +16 planes if g=1
#pragma unroll
    for (int p = 0; p < 4; p++) {
        float ssum = spart[(p << 9) + tid] + spart[(p << 9) + (tid ^ 256)];
        float n = fmaxf(sqrtf(ssum), 1e-7f);
        float f = tanhf(0.1f * n) / (0.1f * n);
        const int gh = gh_base + (p >> 1);
        const int gw = c0 + lane + ((p & 1) << 5);
        float* ob = outb + (gh << 8) + gw;
#pragma unroll
        for (int t = 0; t < 8; t++) {
            float lo, hi;
            unpack2(acc[p][t], lo, hi);
            ob[(size_t)(2 * t) << 16]     = f * lo;
            ob[(size_t)(2 * t + 1) << 16] = f * hi;
        }
    }
}

// ---------------- launch ----------------
extern "C" void kernel_launch(void* const* d_in, const int* in_sizes, int n_in,
                              void* d_out, int out_size) {
    const float* x    = (const float*)d_in[0];
    const float* Wk   = (const float*)d_in[1];
    const float* bias = (const float*)d_in[2];
    float* out = (float*)d_out;

    cudaFuncSetAttribute(pvconv_kernel,
                         cudaFuncAttributeMaxDynamicSharedMemorySize, SMEM_BYTES);

    // kernel 1: per-pixel log0 scale
    log0_scale_kernel<<<(B_SZ * PLANE) / 256, 256>>>(x);

    // kernel 2: fused conv + bias + relu + exp0
    dim3 grid(HW_DIM / TW, HW_DIM / TH, B_SZ);   // (4, 16, 4)
    pvconv_kernel<<<grid, NTHREADS, SMEM_BYTES>>>(x, Wk, bias, out);
}